// round 6
// baseline (speedup 1.0000x reference)
#include <cuda_runtime.h>
#include <cuda_bf16.h>
#include <math.h>
#include <stdint.h>

#define BB   8
#define SRC  512
#define TGT  128
#define DIM  512

// ---------------- scratch (static: allocation-free rule) --------------------
__device__ float g_dp[BB * TGT * DIM];   // 1024 x 512
__device__ float g_mp[BB * SRC * DIM];   // 4096 x 512
__device__ float g_e[BB * TGT * SRC];    // 2 MB, masked scores

__device__ __forceinline__ float fast_tanh(float x) {
    float y;
    asm("tanh.approx.f32 %0, %1;" : "=f"(y) : "f"(x));
    return y;
}
__device__ __forceinline__ uint32_t smem_u32(const void* p) {
    uint32_t a;
    asm("{ .reg .u64 t; cvta.to.shared.u64 t, %1; cvt.u32.u64 %0, t; }"
        : "=r"(a) : "l"(p));
    return a;
}
__device__ __forceinline__ uint32_t cvt_tf32(float f) {
    uint32_t r;
    asm("cvt.rna.tf32.f32 %0, %1;" : "=r"(r) : "f"(f));
    return r;
}
__device__ __forceinline__ void cp_async16(uint32_t dst, const void* src) {
    asm volatile("cp.async.cg.shared.global [%0], [%1], 16;" :: "r"(dst), "l"(src));
}
#define CP_COMMIT()  asm volatile("cp.async.commit_group;" ::: "memory")
#define CP_WAIT(n)   asm volatile("cp.async.wait_group %0;" :: "n"(n) : "memory")

__device__ __forceinline__ void mma_tf32(float* d, uint32_t a0, uint32_t a1,
                                         uint32_t a2, uint32_t a3,
                                         uint32_t b0, uint32_t b1) {
    asm volatile(
        "mma.sync.aligned.m16n8k8.row.col.f32.tf32.tf32.f32 "
        "{%0,%1,%2,%3}, {%4,%5,%6,%7}, {%8,%9}, {%0,%1,%2,%3};"
        : "+f"(d[0]), "+f"(d[1]), "+f"(d[2]), "+f"(d[3])
        : "r"(a0), "r"(a1), "r"(a2), "r"(a3), "r"(b0), "r"(b1));
}

// ---------------------------------------------------------------------------
// tf32 GEMM: C[M x 512] = A[M x 512] @ Wa_half.  CTA tile 64 x 128, KC=32,
// cp.async double buffered. grid (4 n-tiles, 80 m-bands):
//   bands 0-15  -> dp (A=dec,    1024 rows)
//   bands 16-79 -> mp (A=memory, 4096 rows)
// 8 warps in 2(M) x 4(N); warp tile 32x32.
// ---------------------------------------------------------------------------
#define KC        32
#define AS_STRIDE 36
#define BS_STRIDE 136
#define AS_FLOATS (64 * AS_STRIDE)        // 2304
#define BS_FLOATS (KC * BS_STRIDE)        // 4352
#define GEMM_SMEM_BYTES ((2 * AS_FLOATS + 2 * BS_FLOATS) * 4)   // 53248

__device__ __forceinline__ void load_chunk(uint32_t smem_base,
                                           const float* __restrict__ Asrc,
                                           const float* __restrict__ Wbase,
                                           int M0, int kc0, int buf, int tid)
{
    uint32_t abase = smem_base + (uint32_t)(buf * AS_FLOATS) * 4u;
    #pragma unroll
    for (int j = 0; j < 2; j++) {
        int c = tid + j * 256;            // 0..511
        int row = c >> 3, u = c & 7;      // 64 rows x 8 chunks (4 floats)
        cp_async16(abase + (uint32_t)(row * AS_STRIDE + u * 4) * 4u,
                   Asrc + (size_t)(M0 + row) * 512 + kc0 + u * 4);
    }
    uint32_t bbase = smem_base + (uint32_t)(2 * AS_FLOATS + buf * BS_FLOATS) * 4u;
    #pragma unroll
    for (int j = 0; j < 4; j++) {
        int c = tid + j * 256;            // 0..1023
        int kr = c >> 5, u = c & 31;      // 32 k-rows x 32 chunks (4 floats)
        cp_async16(bbase + (uint32_t)(kr * BS_STRIDE + u * 4) * 4u,
                   Wbase + (size_t)(kc0 + kr) * 512 + u * 4);
    }
}

__global__ __launch_bounds__(256)
void tf32_gemm_kernel(const float* __restrict__ memory,
                      const float* __restrict__ dec,
                      const float* __restrict__ Wa)
{
    extern __shared__ float smf[];
    uint32_t smem_base = smem_u32(smf);

    int tid  = threadIdx.x;
    int wid  = tid >> 5;
    int lane = tid & 31;
    int gid  = lane >> 2;   // 0..7
    int tig  = lane & 3;    // 0..3

    int nb = blockIdx.x;    // 0..3
    int mb = blockIdx.y;    // 0..79
    const float* Asrc;
    float* Cbase;
    int half, M0;
    if (mb < 16) { half = 0; Asrc = dec;    Cbase = g_dp; M0 = mb * 64; }
    else         { half = 1; Asrc = memory; Cbase = g_mp; M0 = (mb - 16) * 64; }
    int N0 = nb * 128;
    const float* Wbase = Wa + (size_t)(half * 512) * 512 + N0;

    int wm = (wid & 1) * 32;
    int wn = (wid >> 1) * 32;

    float acc[2][4][4];
    #pragma unroll
    for (int i = 0; i < 2; i++)
        #pragma unroll
        for (int j = 0; j < 4; j++)
            #pragma unroll
            for (int k = 0; k < 4; k++) acc[i][j][k] = 0.f;

    load_chunk(smem_base, Asrc, Wbase, M0, 0, 0, tid);
    CP_COMMIT();

    int buf = 0;
    for (int ck = 0; ck < 16; ck++) {
        if (ck < 15) {
            load_chunk(smem_base, Asrc, Wbase, M0, (ck + 1) * KC, buf ^ 1, tid);
            CP_COMMIT();
            CP_WAIT(1);
        } else {
            CP_WAIT(0);
        }
        __syncthreads();

        const float* As = smf + buf * AS_FLOATS;
        const float* Bs = smf + 2 * AS_FLOATS + buf * BS_FLOATS;

        #pragma unroll
        for (int ks = 0; ks < KC; ks += 8) {
            uint32_t b0[4], b1[4];
            #pragma unroll
            for (int na = 0; na < 4; na++) {
                int bn = wn + na * 8 + gid;
                b0[na] = cvt_tf32(Bs[(ks + tig) * BS_STRIDE + bn]);
                b1[na] = cvt_tf32(Bs[(ks + tig + 4) * BS_STRIDE + bn]);
            }
            #pragma unroll
            for (int ma = 0; ma < 2; ma++) {
                int r = wm + ma * 16 + gid;
                uint32_t a0 = cvt_tf32(As[r * AS_STRIDE + ks + tig]);
                uint32_t a1 = cvt_tf32(As[(r + 8) * AS_STRIDE + ks + tig]);
                uint32_t a2 = cvt_tf32(As[r * AS_STRIDE + ks + tig + 4]);
                uint32_t a3 = cvt_tf32(As[(r + 8) * AS_STRIDE + ks + tig + 4]);
                #pragma unroll
                for (int na = 0; na < 4; na++)
                    mma_tf32(acc[ma][na], a0, a1, a2, a3, b0[na], b1[na]);
            }
        }
        __syncthreads();
        buf ^= 1;
    }

    // ---- epilogue ----
    #pragma unroll
    for (int ma = 0; ma < 2; ma++) {
        #pragma unroll
        for (int na = 0; na < 4; na++) {
            int r0 = M0 + wm + ma * 16 + gid;
            int c0 = N0 + wn + na * 8 + 2 * tig;
            float* p0 = Cbase + (size_t)r0 * 512 + c0;
            float* p1 = Cbase + (size_t)(r0 + 8) * 512 + c0;
            *(float2*)p0 = make_float2(acc[ma][na][0], acc[ma][na][1]);
            *(float2*)p1 = make_float2(acc[ma][na][2], acc[ma][na][3]);
        }
    }
}

// ---------------------------------------------------------------------------
// e_kernel: e[b][t][s] = mask ? sum_k Va[k]*tanh(dp[t][k]+mp[s][k]) : -inf
// grid (4 s-tiles, 16 t-tiles, 8 b) = 512 CTAs, 256 threads (8 warps).
// Each warp handles 16 s rows of its 128-s tile; 8 t per CTA.
// ---------------------------------------------------------------------------
__global__ __launch_bounds__(256)
void e_kernel(const float* __restrict__ Va,
              const int* __restrict__ mask)
{
    __shared__ float dp_s[8][DIM];   // 16 KB
    __shared__ float va_s[DIM];      // 2 KB

    int b  = blockIdx.z;
    int t0 = blockIdx.y * 8;
    int s0 = blockIdx.x * 128;
    int tid  = threadIdx.x;
    int lane = tid & 31;
    int wid  = tid >> 5;             // 0..7

    {
        const float4* src = (const float4*)(g_dp + (size_t)(b * TGT + t0) * DIM);
        float4* dst = (float4*)(&dp_s[0][0]);
        for (int i = tid; i < 8 * DIM / 4; i += 256) dst[i] = src[i];
        const float4* vsrc = (const float4*)Va;
        float4* vdst = (float4*)va_s;
        for (int i = tid; i < DIM / 4; i += 256) vdst[i] = vsrc[i];
    }
    __syncthreads();

    for (int si = wid; si < 128; si += 8) {
        int s = s0 + si;
        const float* mprow = g_mp + (size_t)(b * SRC + s) * DIM;
        float acc[8];
        #pragma unroll
        for (int t = 0; t < 8; t++) acc[t] = 0.f;

        #pragma unroll 4
        for (int ki = 0; ki < 16; ki++) {
            int k = lane + (ki << 5);
            float mv = __ldg(mprow + k);
            float vv = va_s[k];
            #pragma unroll
            for (int t = 0; t < 8; t++)
                acc[t] = fmaf(vv, fast_tanh(dp_s[t][k] + mv), acc[t]);
        }
        #pragma unroll
        for (int t = 0; t < 8; t++) {
            #pragma unroll
            for (int off = 16; off > 0; off >>= 1)
                acc[t] += __shfl_xor_sync(0xffffffffu, acc[t], off);
        }
        if (lane == 0) {
            bool mk = mask[b * SRC + s] != 0;
            float* ep = g_e + (size_t)(b * TGT + t0) * SRC + s;
            #pragma unroll
            for (int t = 0; t < 8; t++)
                ep[(size_t)t * SRC] = mk ? acc[t] : -INFINITY;
        }
    }
}

// ---------------------------------------------------------------------------
// softmax + context: grid (16 t-tiles, 8 b), 512 threads.
// ---------------------------------------------------------------------------
__global__ __launch_bounds__(512)
void softmax_ctx_kernel(const float* __restrict__ memory,
                        float* __restrict__ out)
{
    __shared__ float e_s[8][SRC];    // 16 KB

    int b  = blockIdx.y;
    int t0 = blockIdx.x * 8;
    int tid  = threadIdx.x;
    int lane = tid & 31;
    int wid  = tid >> 5;

    {
        const float4* src = (const float4*)(g_e + (size_t)(b * TGT + t0) * SRC);
        float4* dst = (float4*)(&e_s[0][0]);
        for (int i = tid; i < 8 * SRC / 4; i += 512) dst[i] = src[i];
    }
    __syncthreads();

    if (wid < 8) {
        float mx = -INFINITY;
        for (int i = lane; i < SRC; i += 32) mx = fmaxf(mx, e_s[wid][i]);
        #pragma unroll
        for (int off = 16; off > 0; off >>= 1)
            mx = fmaxf(mx, __shfl_xor_sync(0xffffffffu, mx, off));
        float sum = 0.f;
        for (int i = lane; i < SRC; i += 32) {
            float p = __expf(e_s[wid][i] - mx);
            e_s[wid][i] = p;
            sum += p;
        }
        #pragma unroll
        for (int off = 16; off > 0; off >>= 1)
            sum += __shfl_xor_sync(0xffffffffu, sum, off);
        float inv = 1.f / sum;
        for (int i = lane; i < SRC; i += 32) e_s[wid][i] *= inv;
    }
    __syncthreads();

    int e4 = (tid & 127) * 4;
    int ta = (tid >> 7) * 2;
    int tb = ta + 1;
    float a0x = 0.f, a0y = 0.f, a0z = 0.f, a0w = 0.f;
    float a1x = 0.f, a1y = 0.f, a1z = 0.f, a1w = 0.f;
    const float* memb = memory + (size_t)b * SRC * DIM;
    #pragma unroll 4
    for (int s = 0; s < SRC; s++) {
        float4 mv = *(const float4*)(memb + (size_t)s * DIM + e4);
        float w0 = e_s[ta][s];
        float w1 = e_s[tb][s];
        a0x = fmaf(w0, mv.x, a0x); a0y = fmaf(w0, mv.y, a0y);
        a0z = fmaf(w0, mv.z, a0z); a0w = fmaf(w0, mv.w, a0w);
        a1x = fmaf(w1, mv.x, a1x); a1y = fmaf(w1, mv.y, a1y);
        a1z = fmaf(w1, mv.z, a1z); a1w = fmaf(w1, mv.w, a1w);
    }
    float* o0 = out + (size_t)(b * TGT + t0 + ta) * DIM + e4;
    float* o1 = out + (size_t)(b * TGT + t0 + tb) * DIM + e4;
    *(float4*)o0 = make_float4(a0x, a0y, a0z, a0w);
    *(float4*)o1 = make_float4(a1x, a1y, a1z, a1w);
}

// ---------------------------------------------------------------------------
extern "C" void kernel_launch(void* const* d_in, const int* in_sizes, int n_in,
                              void* d_out, int out_size)
{
    const float* memory = (const float*)d_in[0];
    const float* dec    = (const float*)d_in[1];
    const int*   mask   = (const int*)d_in[2];
    const float* Wa     = (const float*)d_in[3];
    const float* Va     = (const float*)d_in[4];
    float* out = (float*)d_out;

    static int configured = 0;
    if (!configured) {
        cudaFuncSetAttribute(tf32_gemm_kernel,
                             cudaFuncAttributeMaxDynamicSharedMemorySize,
                             GEMM_SMEM_BYTES);
        configured = 1;
    }

    tf32_gemm_kernel<<<dim3(4, 80), 256, GEMM_SMEM_BYTES>>>(memory, dec, Wa);
    e_kernel<<<dim3(4, 16, 8), 256>>>(Va, mask);
    softmax_ctx_kernel<<<dim3(16, 8), 512>>>(memory, out);
}

// round 7
// speedup vs baseline: 1.0701x; 1.0701x over previous
#include <cuda_runtime.h>
#include <cuda_fp16.h>
#include <math.h>
#include <stdint.h>

#define BB   8
#define SRC  512
#define TGT  128
#define DIM  512

// ---------------- scratch (static: allocation-free rule) --------------------
__device__ float g_dp[BB * TGT * DIM];   // 1024 x 512
__device__ float g_mp[BB * SRC * DIM];   // 4096 x 512
__device__ float g_e[BB * TGT * SRC];    // 2 MB, masked scores

__device__ __forceinline__ uint32_t smem_u32(const void* p) {
    uint32_t a;
    asm("{ .reg .u64 t; cvta.to.shared.u64 t, %1; cvt.u32.u64 %0, t; }"
        : "=r"(a) : "l"(p));
    return a;
}
__device__ __forceinline__ uint32_t cvt_tf32(float f) {
    uint32_t r;
    asm("cvt.rna.tf32.f32 %0, %1;" : "=r"(r) : "f"(f));
    return r;
}
__device__ __forceinline__ void cp_async16(uint32_t dst, const void* src) {
    asm volatile("cp.async.cg.shared.global [%0], [%1], 16;" :: "r"(dst), "l"(src));
}
#define CP_COMMIT()  asm volatile("cp.async.commit_group;" ::: "memory")
#define CP_WAIT(n)   asm volatile("cp.async.wait_group %0;" :: "n"(n) : "memory")

__device__ __forceinline__ void mma_tf32(float* d, uint32_t a0, uint32_t a1,
                                         uint32_t a2, uint32_t a3,
                                         uint32_t b0, uint32_t b1) {
    asm volatile(
        "mma.sync.aligned.m16n8k8.row.col.f32.tf32.tf32.f32 "
        "{%0,%1,%2,%3}, {%4,%5,%6,%7}, {%8,%9}, {%0,%1,%2,%3};"
        : "+f"(d[0]), "+f"(d[1]), "+f"(d[2]), "+f"(d[3])
        : "r"(a0), "r"(a1), "r"(a2), "r"(a3), "r"(b0), "r"(b1));
}
__device__ __forceinline__ uint32_t tanh2(uint32_t x) {
    uint32_t y;
    asm("tanh.approx.f16x2 %0, %1;" : "=r"(y) : "r"(x));
    return y;
}

// ---------------------------------------------------------------------------
// tf32 GEMM (unchanged from R6: 32 us measured, tensor pipe 27%).
// CTA tile 64x128, KC=32, cp.async double buffered. grid (4, 80).
// ---------------------------------------------------------------------------
#define KC        32
#define AS_STRIDE 36
#define BS_STRIDE 136
#define AS_FLOATS (64 * AS_STRIDE)
#define BS_FLOATS (KC * BS_STRIDE)
#define GEMM_SMEM_BYTES ((2 * AS_FLOATS + 2 * BS_FLOATS) * 4)   // 53248

__device__ __forceinline__ void load_chunk(uint32_t smem_base,
                                           const float* __restrict__ Asrc,
                                           const float* __restrict__ Wbase,
                                           int M0, int kc0, int buf, int tid)
{
    uint32_t abase = smem_base + (uint32_t)(buf * AS_FLOATS) * 4u;
    #pragma unroll
    for (int j = 0; j < 2; j++) {
        int c = tid + j * 256;
        int row = c >> 3, u = c & 7;
        cp_async16(abase + (uint32_t)(row * AS_STRIDE + u * 4) * 4u,
                   Asrc + (size_t)(M0 + row) * 512 + kc0 + u * 4);
    }
    uint32_t bbase = smem_base + (uint32_t)(2 * AS_FLOATS + buf * BS_FLOATS) * 4u;
    #pragma unroll
    for (int j = 0; j < 4; j++) {
        int c = tid + j * 256;
        int kr = c >> 5, u = c & 31;
        cp_async16(bbase + (uint32_t)(kr * BS_STRIDE + u * 4) * 4u,
                   Wbase + (size_t)(kc0 + kr) * 512 + u * 4);
    }
}

__global__ __launch_bounds__(256)
void tf32_gemm_kernel(const float* __restrict__ memory,
                      const float* __restrict__ dec,
                      const float* __restrict__ Wa)
{
    extern __shared__ float smf[];
    uint32_t smem_base = smem_u32(smf);

    int tid  = threadIdx.x;
    int wid  = tid >> 5;
    int lane = tid & 31;
    int gid  = lane >> 2;
    int tig  = lane & 3;

    int nb = blockIdx.x;
    int mb = blockIdx.y;
    const float* Asrc;
    float* Cbase;
    int half, M0;
    if (mb < 16) { half = 0; Asrc = dec;    Cbase = g_dp; M0 = mb * 64; }
    else         { half = 1; Asrc = memory; Cbase = g_mp; M0 = (mb - 16) * 64; }
    int N0 = nb * 128;
    const float* Wbase = Wa + (size_t)(half * 512) * 512 + N0;

    int wm = (wid & 1) * 32;
    int wn = (wid >> 1) * 32;

    float acc[2][4][4];
    #pragma unroll
    for (int i = 0; i < 2; i++)
        #pragma unroll
        for (int j = 0; j < 4; j++)
            #pragma unroll
            for (int k = 0; k < 4; k++) acc[i][j][k] = 0.f;

    load_chunk(smem_base, Asrc, Wbase, M0, 0, 0, tid);
    CP_COMMIT();

    int buf = 0;
    for (int ck = 0; ck < 16; ck++) {
        if (ck < 15) {
            load_chunk(smem_base, Asrc, Wbase, M0, (ck + 1) * KC, buf ^ 1, tid);
            CP_COMMIT();
            CP_WAIT(1);
        } else {
            CP_WAIT(0);
        }
        __syncthreads();

        const float* As = smf + buf * AS_FLOATS;
        const float* Bs = smf + 2 * AS_FLOATS + buf * BS_FLOATS;

        #pragma unroll
        for (int ks = 0; ks < KC; ks += 8) {
            uint32_t b0[4], b1[4];
            #pragma unroll
            for (int na = 0; na < 4; na++) {
                int bn = wn + na * 8 + gid;
                b0[na] = cvt_tf32(Bs[(ks + tig) * BS_STRIDE + bn]);
                b1[na] = cvt_tf32(Bs[(ks + tig + 4) * BS_STRIDE + bn]);
            }
            #pragma unroll
            for (int ma = 0; ma < 2; ma++) {
                int r = wm + ma * 16 + gid;
                uint32_t a0 = cvt_tf32(As[r * AS_STRIDE + ks + tig]);
                uint32_t a1 = cvt_tf32(As[(r + 8) * AS_STRIDE + ks + tig]);
                uint32_t a2 = cvt_tf32(As[r * AS_STRIDE + ks + tig + 4]);
                uint32_t a3 = cvt_tf32(As[(r + 8) * AS_STRIDE + ks + tig + 4]);
                #pragma unroll
                for (int na = 0; na < 4; na++)
                    mma_tf32(acc[ma][na], a0, a1, a2, a3, b0[na], b1[na]);
            }
        }
        __syncthreads();
        buf ^= 1;
    }

    #pragma unroll
    for (int ma = 0; ma < 2; ma++) {
        #pragma unroll
        for (int na = 0; na < 4; na++) {
            int r0 = M0 + wm + ma * 16 + gid;
            int c0 = N0 + wn + na * 8 + 2 * tig;
            float* p0 = Cbase + (size_t)r0 * 512 + c0;
            float* p1 = Cbase + (size_t)(r0 + 8) * 512 + c0;
            *(float2*)p0 = make_float2(acc[ma][na][0], acc[ma][na][1]);
            *(float2*)p1 = make_float2(acc[ma][na][2], acc[ma][na][3]);
        }
    }
}

// ---------------------------------------------------------------------------
// e_kernel with f16x2 tanh: e[b][t][s] = mask ? sum_k Va[k]*tanh(dp+mp) : -inf
// dp packed to f16x2 in smem; mp packed per pair; accumulate in f32.
// grid (4 s-tiles, 16 t-tiles, 8 b) = 512 CTAs, 256 threads.
// ---------------------------------------------------------------------------
__global__ __launch_bounds__(256)
void e_kernel(const float* __restrict__ Va,
              const int* __restrict__ mask)
{
    __shared__ uint32_t dp_h[8][256];   // 8 rows x 256 f16x2 pairs, 8 KB
    __shared__ float2 va2_s[256];       // 2 KB

    int b  = blockIdx.z;
    int t0 = blockIdx.y * 8;
    int s0 = blockIdx.x * 128;
    int tid  = threadIdx.x;
    int lane = tid & 31;
    int wid  = tid >> 5;                // 0..7

    // pack dp tile (8 x 512 f32 -> 8 x 256 f16x2) and load Va as float2
    for (int i = tid; i < 8 * 256; i += 256) {
        int t = i >> 8, p = i & 255;
        float2 v = *(const float2*)(g_dp + (size_t)(b * TGT + t0 + t) * DIM + 2 * p);
        __half2 h = __float22half2_rn(v);
        dp_h[t][p] = *reinterpret_cast<uint32_t*>(&h);
    }
    {
        int p = tid;                     // 256 threads, 256 pairs
        va2_s[p] = *(const float2*)(Va + 2 * p);
    }
    __syncthreads();

    for (int si = wid; si < 128; si += 8) {
        int s = s0 + si;
        const float2* mp2 = (const float2*)(g_mp + (size_t)(b * SRC + s) * DIM);
        float acc[8];
        #pragma unroll
        for (int t = 0; t < 8; t++) acc[t] = 0.f;

        #pragma unroll
        for (int pi = 0; pi < 8; pi++) {
            int p = lane + (pi << 5);
            float2 m = __ldg(mp2 + p);
            __half2 mh = __float22half2_rn(m);
            uint32_t mhu = *reinterpret_cast<uint32_t*>(&mh);
            float2 va2 = va2_s[p];
            #pragma unroll
            for (int t = 0; t < 8; t++) {
                uint32_t du = dp_h[t][p];
                __half2 d = *reinterpret_cast<__half2*>(&du);
                __half2 mm = *reinterpret_cast<__half2*>(&mhu);
                __half2 x = __hadd2(d, mm);
                uint32_t yu = tanh2(*reinterpret_cast<uint32_t*>(&x));
                float2 tv = __half22float2(*reinterpret_cast<__half2*>(&yu));
                acc[t] = fmaf(va2.x, tv.x, acc[t]);
                acc[t] = fmaf(va2.y, tv.y, acc[t]);
            }
        }
        #pragma unroll
        for (int t = 0; t < 8; t++) {
            #pragma unroll
            for (int off = 16; off > 0; off >>= 1)
                acc[t] += __shfl_xor_sync(0xffffffffu, acc[t], off);
        }
        if (lane == 0) {
            bool mk = mask[b * SRC + s] != 0;
            float* ep = g_e + (size_t)(b * TGT + t0) * SRC + s;
            #pragma unroll
            for (int t = 0; t < 8; t++)
                ep[(size_t)t * SRC] = mk ? acc[t] : -INFINITY;
        }
    }
}

// ---------------------------------------------------------------------------
// softmax + context: grid (16 t-tiles, 8 b, 2 e-halves), 256 threads.
// Softmax (cheap) recomputed by both halves; context covers 256 dims each.
// ---------------------------------------------------------------------------
__global__ __launch_bounds__(256)
void softmax_ctx_kernel(const float* __restrict__ memory,
                        float* __restrict__ out)
{
    __shared__ float e_s[8][SRC];    // 16 KB

    int b   = blockIdx.y;
    int t0  = blockIdx.x * 8;
    int eh  = blockIdx.z;            // 0 or 1
    int tid  = threadIdx.x;
    int lane = tid & 31;
    int wid  = tid >> 5;             // 0..7

    {
        const float4* src = (const float4*)(g_e + (size_t)(b * TGT + t0) * SRC);
        float4* dst = (float4*)(&e_s[0][0]);
        for (int i = tid; i < 8 * SRC / 4; i += 256) dst[i] = src[i];
    }
    __syncthreads();

    {   // 8 warps, one t-row each
        float mx = -INFINITY;
        for (int i = lane; i < SRC; i += 32) mx = fmaxf(mx, e_s[wid][i]);
        #pragma unroll
        for (int off = 16; off > 0; off >>= 1)
            mx = fmaxf(mx, __shfl_xor_sync(0xffffffffu, mx, off));
        float sum = 0.f;
        for (int i = lane; i < SRC; i += 32) {
            float p = __expf(e_s[wid][i] - mx);
            e_s[wid][i] = p;
            sum += p;
        }
        #pragma unroll
        for (int off = 16; off > 0; off >>= 1)
            sum += __shfl_xor_sync(0xffffffffu, sum, off);
        float inv = 1.f / sum;
        for (int i = lane; i < SRC; i += 32) e_s[wid][i] *= inv;
    }
    __syncthreads();

    int e4 = (tid & 63) * 4 + eh * 256;
    int ta = (tid >> 6) * 2;
    int tb = ta + 1;
    float a0x = 0.f, a0y = 0.f, a0z = 0.f, a0w = 0.f;
    float a1x = 0.f, a1y = 0.f, a1z = 0.f, a1w = 0.f;
    const float* memb = memory + (size_t)b * SRC * DIM;
    #pragma unroll 4
    for (int s = 0; s < SRC; s++) {
        float4 mv = *(const float4*)(memb + (size_t)s * DIM + e4);
        float w0 = e_s[ta][s];
        float w1 = e_s[tb][s];
        a0x = fmaf(w0, mv.x, a0x); a0y = fmaf(w0, mv.y, a0y);
        a0z = fmaf(w0, mv.z, a0z); a0w = fmaf(w0, mv.w, a0w);
        a1x = fmaf(w1, mv.x, a1x); a1y = fmaf(w1, mv.y, a1y);
        a1z = fmaf(w1, mv.z, a1z); a1w = fmaf(w1, mv.w, a1w);
    }
    float* o0 = out + (size_t)(b * TGT + t0 + ta) * DIM + e4;
    float* o1 = out + (size_t)(b * TGT + t0 + tb) * DIM + e4;
    *(float4*)o0 = make_float4(a0x, a0y, a0z, a0w);
    *(float4*)o1 = make_float4(a1x, a1y, a1z, a1w);
}

// ---------------------------------------------------------------------------
extern "C" void kernel_launch(void* const* d_in, const int* in_sizes, int n_in,
                              void* d_out, int out_size)
{
    const float* memory = (const float*)d_in[0];
    const float* dec    = (const float*)d_in[1];
    const int*   mask   = (const int*)d_in[2];
    const float* Wa     = (const float*)d_in[3];
    const float* Va     = (const float*)d_in[4];
    float* out = (float*)d_out;

    static int configured = 0;
    if (!configured) {
        cudaFuncSetAttribute(tf32_gemm_kernel,
                             cudaFuncAttributeMaxDynamicSharedMemorySize,
                             GEMM_SMEM_BYTES);
        configured = 1;
    }

    tf32_gemm_kernel<<<dim3(4, 80), 256, GEMM_SMEM_BYTES>>>(memory, dec, Wa);
    e_kernel<<<dim3(4, 16, 8), 256>>>(Va, mask);
    softmax_ctx_kernel<<<dim3(16, 8, 2), 256>>>(memory, out);
}

// round 10
// speedup vs baseline: 1.3985x; 1.3069x over previous
#include <cuda_runtime.h>
#include <cuda_fp16.h>
#include <math.h>
#include <stdint.h>

#define BB   8
#define SRC  512
#define TGT  128
#define DIM  512

// ---------------- scratch (static: allocation-free rule) --------------------
__device__ uint32_t g_dp_h[BB * TGT * 256];   // 1 MB, half2-packed dp
__device__ uint32_t g_mp_h[BB * SRC * 256];   // 4 MB, half2-packed mp
__device__ float    g_e[BB * TGT * SRC];      // 2 MB, masked scores
__device__ float    g_a[BB * TGT * SRC];      // 2 MB, softmax weights

__device__ __forceinline__ uint32_t smem_u32(const void* p) {
    uint32_t a;
    asm("{ .reg .u64 t; cvta.to.shared.u64 t, %1; cvt.u32.u64 %0, t; }"
        : "=r"(a) : "l"(p));
    return a;
}
__device__ __forceinline__ uint32_t cvt_tf32(float f) {
    uint32_t r;
    asm("cvt.rna.tf32.f32 %0, %1;" : "=r"(r) : "f"(f));
    return r;
}
__device__ __forceinline__ void cp_async16(uint32_t dst, const void* src) {
    asm volatile("cp.async.cg.shared.global [%0], [%1], 16;" :: "r"(dst), "l"(src));
}
#define CP_COMMIT()  asm volatile("cp.async.commit_group;" ::: "memory")
#define CP_WAIT(n)   asm volatile("cp.async.wait_group %0;" :: "n"(n) : "memory")

__device__ __forceinline__ void mma_tf32(float* d, uint32_t a0, uint32_t a1,
                                         uint32_t a2, uint32_t a3,
                                         uint32_t b0, uint32_t b1) {
    asm volatile(
        "mma.sync.aligned.m16n8k8.row.col.f32.tf32.tf32.f32 "
        "{%0,%1,%2,%3}, {%4,%5,%6,%7}, {%8,%9}, {%0,%1,%2,%3};"
        : "+f"(d[0]), "+f"(d[1]), "+f"(d[2]), "+f"(d[3])
        : "r"(a0), "r"(a1), "r"(a2), "r"(a3), "r"(b0), "r"(b1));
}
__device__ __forceinline__ uint32_t tanh2(uint32_t x) {
    uint32_t y;
    asm("tanh.approx.f16x2 %0, %1;" : "=r"(y) : "r"(x));
    return y;
}
__device__ __forceinline__ uint32_t pack_h2(float a, float b) {
    __half2 h = __floats2half2_rn(a, b);
    return *reinterpret_cast<uint32_t*>(&h);
}

// ---------------------------------------------------------------------------
// Shared cp.async chunk loader (A: 64 x 32 f32 rows stride 512; B: 32 x 128).
// ---------------------------------------------------------------------------
#define KC        32
#define AS_STRIDE 36
#define BS_STRIDE 136
#define AS_FLOATS (64 * AS_STRIDE)
#define BS_FLOATS (KC * BS_STRIDE)
#define GEMM_SMEM_BYTES ((2 * AS_FLOATS + 2 * BS_FLOATS) * 4)   // 53248

__device__ __forceinline__ void load_chunk(uint32_t smem_base,
                                           const float* __restrict__ Asrc,
                                           const float* __restrict__ Bsrc,
                                           int M0, int kc0, int buf, int tid)
{
    uint32_t abase = smem_base + (uint32_t)(buf * AS_FLOATS) * 4u;
    #pragma unroll
    for (int j = 0; j < 2; j++) {
        int c = tid + j * 256;
        int row = c >> 3, u = c & 7;
        cp_async16(abase + (uint32_t)(row * AS_STRIDE + u * 4) * 4u,
                   Asrc + (size_t)(M0 + row) * 512 + kc0 + u * 4);
    }
    uint32_t bbase = smem_base + (uint32_t)(2 * AS_FLOATS + buf * BS_FLOATS) * 4u;
    #pragma unroll
    for (int j = 0; j < 4; j++) {
        int c = tid + j * 256;
        int kr = c >> 5, u = c & 31;
        cp_async16(bbase + (uint32_t)(kr * BS_STRIDE + u * 4) * 4u,
                   Bsrc + (size_t)(kc0 + kr) * 512 + u * 4);
    }
}

// ---------------------------------------------------------------------------
// dp/mp tf32 GEMM, epilogue packs half2 into g_dp_h/g_mp_h. grid (4, 80).
// ---------------------------------------------------------------------------
__global__ __launch_bounds__(256)
void tf32_gemm_kernel(const float* __restrict__ memory,
                      const float* __restrict__ dec,
                      const float* __restrict__ Wa)
{
    extern __shared__ float smf[];
    uint32_t smem_base = smem_u32(smf);

    int tid  = threadIdx.x;
    int wid  = tid >> 5;
    int lane = tid & 31;
    int gid  = lane >> 2;
    int tig  = lane & 3;

    int nb = blockIdx.x;
    int mb = blockIdx.y;
    const float* Asrc;
    uint32_t* Cbase;
    int half, M0;
    if (mb < 16) { half = 0; Asrc = dec;    Cbase = g_dp_h; M0 = mb * 64; }
    else         { half = 1; Asrc = memory; Cbase = g_mp_h; M0 = (mb - 16) * 64; }
    int N0 = nb * 128;
    const float* Wbase = Wa + (size_t)(half * 512) * 512 + N0;

    int wm = (wid & 1) * 32;
    int wn = (wid >> 1) * 32;

    float acc[2][4][4];
    #pragma unroll
    for (int i = 0; i < 2; i++)
        #pragma unroll
        for (int j = 0; j < 4; j++)
            #pragma unroll
            for (int k = 0; k < 4; k++) acc[i][j][k] = 0.f;

    load_chunk(smem_base, Asrc, Wbase, M0, 0, 0, tid);
    CP_COMMIT();

    int buf = 0;
    for (int ck = 0; ck < 16; ck++) {
        if (ck < 15) {
            load_chunk(smem_base, Asrc, Wbase, M0, (ck + 1) * KC, buf ^ 1, tid);
            CP_COMMIT();
            CP_WAIT(1);
        } else {
            CP_WAIT(0);
        }
        __syncthreads();

        const float* As = smf + buf * AS_FLOATS;
        const float* Bs = smf + 2 * AS_FLOATS + buf * BS_FLOATS;

        #pragma unroll
        for (int ks = 0; ks < KC; ks += 8) {
            uint32_t b0[4], b1[4];
            #pragma unroll
            for (int na = 0; na < 4; na++) {
                int bn = wn + na * 8 + gid;
                b0[na] = cvt_tf32(Bs[(ks + tig) * BS_STRIDE + bn]);
                b1[na] = cvt_tf32(Bs[(ks + tig + 4) * BS_STRIDE + bn]);
            }
            #pragma unroll
            for (int ma = 0; ma < 2; ma++) {
                int r = wm + ma * 16 + gid;
                uint32_t a0 = cvt_tf32(As[r * AS_STRIDE + ks + tig]);
                uint32_t a1 = cvt_tf32(As[(r + 8) * AS_STRIDE + ks + tig]);
                uint32_t a2 = cvt_tf32(As[r * AS_STRIDE + ks + tig + 4]);
                uint32_t a3 = cvt_tf32(As[(r + 8) * AS_STRIDE + ks + tig + 4]);
                #pragma unroll
                for (int na = 0; na < 4; na++)
                    mma_tf32(acc[ma][na], a0, a1, a2, a3, b0[na], b1[na]);
            }
        }
        __syncthreads();
        buf ^= 1;
    }

    // epilogue: pack pairs (c0, c0+1) into half2 words
    #pragma unroll
    for (int ma = 0; ma < 2; ma++) {
        #pragma unroll
        for (int na = 0; na < 4; na++) {
            int r0 = M0 + wm + ma * 16 + gid;
            int c0 = N0 + wn + na * 8 + 2 * tig;   // even
            Cbase[(size_t)r0 * 256 + (c0 >> 1)] =
                pack_h2(acc[ma][na][0], acc[ma][na][1]);
            Cbase[(size_t)(r0 + 8) * 256 + (c0 >> 1)] =
                pack_h2(acc[ma][na][2], acc[ma][na][3]);
        }
    }
}

// ---------------------------------------------------------------------------
// e_kernel: HADD2 + TANH2 + HFMA2 inner loop, f16 block accumulation
// (promote to f32 every 4 pairs). grid (4 s-tiles, 16 t-tiles, 8 b), 256 thr.
// ---------------------------------------------------------------------------
__global__ __launch_bounds__(256)
void e_kernel(const float* __restrict__ Va,
              const int* __restrict__ mask)
{
    __shared__ uint32_t dp_h[8][256];   // 8 KB

    int b  = blockIdx.z;
    int t0 = blockIdx.y * 8;
    int s0 = blockIdx.x * 128;
    int tid  = threadIdx.x;
    int lane = tid & 31;
    int wid  = tid >> 5;                // 0..7

    // dp tile: straight uint32 copy of pre-packed half2
    for (int i = tid; i < 8 * 256; i += 256)
        dp_h[i >> 8][i & 255] = g_dp_h[(size_t)(b * TGT + t0 + (i >> 8)) * 256 + (i & 255)];

    // Va pairs for this lane, packed to half2 regs
    uint32_t va_h2[8];
    #pragma unroll
    for (int pi = 0; pi < 8; pi++) {
        int p = lane + (pi << 5);
        float2 v = __ldg((const float2*)(Va) + p);
        va_h2[pi] = pack_h2(v.x, v.y);
    }
    __syncthreads();

    const __half2 zero2 = __float2half2_rn(0.f);

    for (int si = wid; si < 128; si += 8) {
        int s = s0 + si;
        const uint32_t* mprow = g_mp_h + (size_t)(b * SRC + s) * 256;
        __half2 acch[8];
        float accf[8];
        #pragma unroll
        for (int t = 0; t < 8; t++) { acch[t] = zero2; accf[t] = 0.f; }

        #pragma unroll
        for (int pi = 0; pi < 8; pi++) {
            int p = lane + (pi << 5);
            uint32_t mu = __ldg(mprow + p);
            __half2 m2 = *reinterpret_cast<__half2*>(&mu);
            __half2 va2 = *reinterpret_cast<__half2*>(&va_h2[pi]);
            #pragma unroll
            for (int t = 0; t < 8; t++) {
                uint32_t du = dp_h[t][p];
                __half2 x = __hadd2(*reinterpret_cast<__half2*>(&du), m2);
                uint32_t yu = tanh2(*reinterpret_cast<uint32_t*>(&x));
                acch[t] = __hfma2(*reinterpret_cast<__half2*>(&yu), va2, acch[t]);
            }
            if (pi == 3 || pi == 7) {
                #pragma unroll
                for (int t = 0; t < 8; t++) {
                    float2 f = __half22float2(acch[t]);
                    accf[t] += f.x + f.y;
                    acch[t] = zero2;
                }
            }
        }
        #pragma unroll
        for (int t = 0; t < 8; t++) {
            #pragma unroll
            for (int off = 16; off > 0; off >>= 1)
                accf[t] += __shfl_xor_sync(0xffffffffu, accf[t], off);
        }
        if (lane == 0) {
            bool mk = mask[b * SRC + s] != 0;
            float* ep = g_e + (size_t)(b * TGT + t0) * SRC + s;
            #pragma unroll
            for (int t = 0; t < 8; t++)
                ep[(size_t)t * SRC] = mk ? accf[t] : -INFINITY;
        }
    }
}

// ---------------------------------------------------------------------------
// softmax: one warp per t-row (1024 rows total), writes g_a. grid 128, 256 thr.
// ---------------------------------------------------------------------------
__global__ __launch_bounds__(256)
void softmax_kernel()
{
    int row  = blockIdx.x * 8 + (threadIdx.x >> 5);   // 0..1023
    int lane = threadIdx.x & 31;
    const float* ep = g_e + (size_t)row * SRC;
    float*       ap = g_a + (size_t)row * SRC;

    float v[16];
    float mx = -INFINITY;
    #pragma unroll
    for (int i = 0; i < 4; i++) {
        float4 t = *(const float4*)(ep + lane * 4 + i * 128);
        v[i * 4 + 0] = t.x; v[i * 4 + 1] = t.y;
        v[i * 4 + 2] = t.z; v[i * 4 + 3] = t.w;
        mx = fmaxf(mx, fmaxf(fmaxf(t.x, t.y), fmaxf(t.z, t.w)));
    }
    #pragma unroll
    for (int off = 16; off > 0; off >>= 1)
        mx = fmaxf(mx, __shfl_xor_sync(0xffffffffu, mx, off));
    float sum = 0.f;
    #pragma unroll
    for (int i = 0; i < 16; i++) { v[i] = __expf(v[i] - mx); sum += v[i]; }
    #pragma unroll
    for (int off = 16; off > 0; off >>= 1)
        sum += __shfl_xor_sync(0xffffffffu, sum, off);
    float inv = 1.f / sum;
    #pragma unroll
    for (int i = 0; i < 4; i++) {
        float4 t = make_float4(v[i * 4] * inv, v[i * 4 + 1] * inv,
                               v[i * 4 + 2] * inv, v[i * 4 + 3] * inv);
        *(float4*)(ap + lane * 4 + i * 128) = t;
    }
}

// ---------------------------------------------------------------------------
// ctx tf32 GEMM: out[b] = g_a[b] (128x512) @ memory[b] (512x512).
// grid (4 n-tiles, 2 m-tiles, 8 b), same skeleton as tf32_gemm_kernel.
// ---------------------------------------------------------------------------
__global__ __launch_bounds__(256)
void ctx_gemm_kernel(const float* __restrict__ memory, float* __restrict__ out)
{
    extern __shared__ float smf[];
    uint32_t smem_base = smem_u32(smf);

    int tid  = threadIdx.x;
    int wid  = tid >> 5;
    int lane = tid & 31;
    int gid  = lane >> 2;
    int tig  = lane & 3;

    int nb = blockIdx.x;               // 0..3
    int mb = blockIdx.y;               // 0..1
    int b  = blockIdx.z;
    int M0 = mb * 64;
    int N0 = nb * 128;
    const float* Asrc = g_a + (size_t)b * TGT * SRC;
    const float* Bsrc = memory + (size_t)b * SRC * DIM + N0;
    float* Cb = out + (size_t)b * TGT * DIM;

    int wm = (wid & 1) * 32;
    int wn = (wid >> 1) * 32;

    float acc[2][4][4];
    #pragma unroll
    for (int i = 0; i < 2; i++)
        #pragma unroll
        for (int j = 0; j < 4; j++)
            #pragma unroll
            for (int k = 0; k < 4; k++) acc[i][j][k] = 0.f;

    load_chunk(smem_base, Asrc, Bsrc, M0, 0, 0, tid);
    CP_COMMIT();

    int buf = 0;
    for (int ck = 0; ck < 16; ck++) {
        if (ck < 15) {
            load_chunk(smem_base, Asrc, Bsrc, M0, (ck + 1) * KC, buf ^ 1, tid);
            CP_COMMIT();
            CP_WAIT(1);
        } else {
            CP_WAIT(0);
        }
        __syncthreads();

        const float* As = smf + buf * AS_FLOATS;
        const float* Bs = smf + 2 * AS_FLOATS + buf * BS_FLOATS;

        #pragma unroll
        for (int ks = 0; ks < KC; ks += 8) {
            uint32_t b0[4], b1[4];
            #pragma unroll
            for (int na = 0; na < 4; na++) {
                int bn = wn + na * 8 + gid;
                b0[na] = cvt_tf32(Bs[(ks + tig) * BS_STRIDE + bn]);
                b1[na] = cvt_tf32(Bs[(ks + tig + 4) * BS_STRIDE + bn]);
            }
            #pragma unroll
            for (int ma = 0; ma < 2; ma++) {
                int r = wm + ma * 16 + gid;
                uint32_t a0 = cvt_tf32(As[r * AS_STRIDE + ks + tig]);
                uint32_t a1 = cvt_tf32(As[(r + 8) * AS_STRIDE + ks + tig]);
                uint32_t a2 = cvt_tf32(As[r * AS_STRIDE + ks + tig + 4]);
                uint32_t a3 = cvt_tf32(As[(r + 8) * AS_STRIDE + ks + tig + 4]);
                #pragma unroll
                for (int na = 0; na < 4; na++)
                    mma_tf32(acc[ma][na], a0, a1, a2, a3, b0[na], b1[na]);
            }
        }
        __syncthreads();
        buf ^= 1;
    }

    #pragma unroll
    for (int ma = 0; ma < 2; ma++) {
        #pragma unroll
        for (int na = 0; na < 4; na++) {
            int r0 = M0 + wm + ma * 16 + gid;
            int c0 = N0 + wn + na * 8 + 2 * tig;
            float* p0 = Cb + (size_t)r0 * 512 + c0;
            float* p1 = Cb + (size_t)(r0 + 8) * 512 + c0;
            *(float2*)p0 = make_float2(acc[ma][na][0], acc[ma][na][1]);
            *(float2*)p1 = make_float2(acc[ma][na][2], acc[ma][na][3]);
        }
    }
}

// ---------------------------------------------------------------------------
extern "C" void kernel_launch(void* const* d_in, const int* in_sizes, int n_in,
                              void* d_out, int out_size)
{
    const float* memory = (const float*)d_in[0];
    const float* dec    = (const float*)d_in[1];
    const int*   mask   = (const int*)d_in[2];
    const float* Wa     = (const float*)d_in[3];
    const float* Va     = (const float*)d_in[4];
    float* out = (float*)d_out;

    static int configured = 0;
    if (!configured) {
        cudaFuncSetAttribute(tf32_gemm_kernel,
                             cudaFuncAttributeMaxDynamicSharedMemorySize,
                             GEMM_SMEM_BYTES);
        cudaFuncSetAttribute(ctx_gemm_kernel,
                             cudaFuncAttributeMaxDynamicSharedMemorySize,
                             GEMM_SMEM_BYTES);
        configured = 1;
    }

    tf32_gemm_kernel<<<dim3(4, 80), 256, GEMM_SMEM_BYTES>>>(memory, dec, Wa);
    e_kernel<<<dim3(4, 16, 8), 256>>>(Va, mask);
    softmax_kernel<<<128, 256>>>();
    ctx_gemm_kernel<<<dim3(4, 2, 8), 256, GEMM_SMEM_BYTES>>>(memory, out);
}